// round 1
// baseline (speedup 1.0000x reference)
#include <cuda_runtime.h>
#include <cstdint>

#define BB 4
#define NN 8192
#define CIN 64
#define CC 128
#define MM 2048
#define KK 32
#define LL 2

// ---------------- scratch (static device globals; no allocation) ----------------
__device__ float  g_feats[BB*NN*CC];     // 16 MB  post x_mlp features (b,n,C)
__device__ float  g_xf[BB*MM*CC];
__device__ float  g_t1[BB*MM*CC];
__device__ float  g_t2[BB*MM*CC];
__device__ float  g_centbuf[BB*MM*3];
__device__ int    g_nbr1[BB*MM*KK];
__device__ int    g_nbr2[BB*MM*KK];
__device__ double g_sum[CC], g_sqs[CC];
__device__ double g_m1[3],  g_m2[6];
__device__ float  g_scale[CC], g_shift[CC];
__device__ float  g_scps[CC], g_shps[CC];
__device__ float  g_scpe[CC], g_shpe[CC];

// ---------------- FPS: exact match of jax scan (argmax first-index ties) --------
__global__ void __launch_bounds__(1024) fps_kernel(const float* __restrict__ pos,
                                                   float* __restrict__ cent) {
    int b = blockIdx.x;
    const float* P = pos + (size_t)b * NN * 3;
    int t = threadIdx.x;
    const int PT = NN / 1024;  // 8 points per thread, strided
    float px[PT], py[PT], pz[PT], dd[PT];
#pragma unroll
    for (int j = 0; j < PT; j++) {
        int i = t + j * 1024;
        px[j] = P[i*3]; py[j] = P[i*3+1]; pz[j] = P[i*3+2];
        dd[j] = 1e10f;
    }
    __shared__ unsigned long long red[32];
    __shared__ int   s_last;
    __shared__ float s_lp[3];
    if (t == 0) s_last = 0;
    __syncthreads();

    for (int m = 0; m < MM; m++) {
        if (t == 0) {
            int l = s_last;
            float lx = P[l*3], ly = P[l*3+1], lz = P[l*3+2];
            s_lp[0] = lx; s_lp[1] = ly; s_lp[2] = lz;
            float* co = cent + ((size_t)b*MM + m) * 3;
            co[0] = lx; co[1] = ly; co[2] = lz;
        }
        __syncthreads();
        float lx = s_lp[0], ly = s_lp[1], lz = s_lp[2];
        unsigned long long best = 0ull;
#pragma unroll
        for (int j = 0; j < PT; j++) {
            float dx = px[j] - lx, dy = py[j] - ly, dz = pz[j] - lz;
            // exact ((dx^2 + dy^2) + dz^2), no FMA contraction
            float d = __fadd_rn(__fadd_rn(__fmul_rn(dx,dx), __fmul_rn(dy,dy)),
                                __fmul_rn(dz,dz));
            float nd = fminf(dd[j], d);
            dd[j] = nd;
            unsigned long long key =
                ((unsigned long long)__float_as_uint(nd) << 32) |
                (unsigned)(NN - (t + j * 1024));   // tie -> smaller index wins
            best = best > key ? best : key;
        }
#pragma unroll
        for (int off = 16; off > 0; off >>= 1) {
            unsigned long long o = __shfl_down_sync(0xffffffffu, best, off);
            best = best > o ? best : o;
        }
        int lane = t & 31, wid = t >> 5;
        if (lane == 0) red[wid] = best;
        __syncthreads();
        if (wid == 0) {
            unsigned long long v = red[lane];
#pragma unroll
            for (int off = 16; off > 0; off >>= 1) {
                unsigned long long o = __shfl_down_sync(0xffffffffu, v, off);
                v = v > o ? v : o;
            }
            if (lane == 0) s_last = NN - (int)(v & 0xffffffffull);
        }
        __syncthreads();
    }
}

// ---------------- generic small GEMM: Y[r,o] = sum_c A[r,c] * W[o,c] ------------
template <int CINT>
__global__ void __launch_bounds__(128) gemm_kernel(const float* __restrict__ A,
                                                   const float* __restrict__ W,
                                                   float* __restrict__ Y) {
    extern __shared__ float sm[];
    float* Wt = sm;             // [CINT][128] transposed
    float* At = sm + CINT*128;  // [32][CINT]
    int t = threadIdx.x;
    for (int idx = t; idx < 128*CINT; idx += 128) {
        int o = idx / CINT, c = idx - o*CINT;
        Wt[c*128 + o] = W[idx];
    }
    size_t row0 = (size_t)blockIdx.x * 32;
    const float* Ab = A + row0 * CINT;
    for (int idx = t; idx < 32*CINT; idx += 128) At[idx] = Ab[idx];
    __syncthreads();
    float acc[32];
#pragma unroll
    for (int r = 0; r < 32; r++) acc[r] = 0.f;
    for (int c = 0; c < CINT; c++) {
        float w = Wt[c*128 + t];
#pragma unroll
        for (int r = 0; r < 32; r++) acc[r] = fmaf(At[r*CINT + c], w, acc[r]);
    }
#pragma unroll
    for (int r = 0; r < 32; r++) Y[(row0 + r)*128 + t] = acc[r];
}

// ---------------- BN stats over rows (per 128-channel) --------------------------
__global__ void zero_stats_kernel() {
    int t = threadIdx.x;
    g_sum[t] = 0.0; g_sqs[t] = 0.0;
}

__global__ void __launch_bounds__(128) stats_kernel(const float* __restrict__ Y, int rpb) {
    int t = threadIdx.x;
    size_t r0 = (size_t)blockIdx.x * rpb;
    float s = 0.f, q = 0.f;
    for (int r = 0; r < rpb; r++) {
        float v = Y[(r0 + r)*128 + t];
        s += v; q = fmaf(v, v, q);
    }
    atomicAdd(&g_sum[t], (double)s);
    atomicAdd(&g_sqs[t], (double)q);
}

__global__ void finalize_kernel(const float* __restrict__ gam,
                                const float* __restrict__ bet, double invcnt) {
    int c = threadIdx.x;
    double mean = g_sum[c] * invcnt;
    double var  = g_sqs[c] * invcnt - mean * mean;
    double s = (double)gam[c] * rsqrt(var + 1e-5);
    g_scale[c] = (float)s;
    g_shift[c] = (float)((double)bet[c] - mean * s);
}

__global__ void affine_relu_kernel(float* __restrict__ X, int ntot) {
    int i = blockIdx.x * blockDim.x + threadIdx.x;
    if (i < ntot) {
        int c = i & 127;
        X[i] = fmaxf(fmaf(X[i], g_scale[c], g_shift[c]), 0.f);
    }
}

// ---------------- ball query: first K indices with d2 < r2 (exact) --------------
__global__ void bq_kernel(const float* __restrict__ q, const float* __restrict__ pts,
                          int np, float r2, int* __restrict__ nbr) {
    int gw = (blockIdx.x * blockDim.x + threadIdx.x) >> 5;
    int lane = threadIdx.x & 31;
    if (gw >= BB*MM) return;
    int b = gw >> 11;  // MM = 2048
    const float* Q = q + (size_t)gw * 3;
    float qx = Q[0], qy = Q[1], qz = Q[2];
    const float* P = pts + (size_t)b * np * 3;
    int cnt = 0, first = 0;
    for (int base = 0; base < np; base += 32) {
        int i = base + lane;
        float dx = qx - P[i*3], dy = qy - P[i*3+1], dz = qz - P[i*3+2];
        float d2 = __fadd_rn(__fadd_rn(__fmul_rn(dx,dx), __fmul_rn(dy,dy)),
                             __fmul_rn(dz,dz));
        bool pred = d2 < r2;
        unsigned mask = __ballot_sync(0xffffffffu, pred);
        if (cnt == 0 && mask) first = base + __ffs(mask) - 1;
        if (pred) {
            int pos = cnt + __popc(mask & ((1u << lane) - 1u));
            if (pos < KK) nbr[(size_t)gw*KK + pos] = i;
        }
        cnt += __popc(mask);
        if (cnt >= KK) break;
    }
    for (int k = cnt + lane; k < KK; k += 32) nbr[(size_t)gw*KK + k] = first;
}

// ---------------- 3-dim offset moments (for analytic BN of W_ps/W_pe convs) -----
__global__ void zero_moments_kernel() {
    int t = threadIdx.x;
    if (t < 3) g_m1[t] = 0.0;
    if (t < 6) g_m2[t] = 0.0;
}

__global__ void moments_kernel(const int* __restrict__ nbr, const float* __restrict__ pts,
                               const float* __restrict__ cent, float R, int np) {
    int idx = blockIdx.x * blockDim.x + threadIdx.x;  // BB*MM*KK total
    int bm = idx / KK;
    int b = bm >> 11;
    int j = nbr[idx];
    float cx = cent[(size_t)bm*3], cy = cent[(size_t)bm*3+1], cz = cent[(size_t)bm*3+2];
    const float* p = pts + ((size_t)b*np + j) * 3;
    float v0 = (p[0]-cx)/R, v1 = (p[1]-cy)/R, v2 = (p[2]-cz)/R;
    double a[9] = { v0, v1, v2,
                    (double)v0*v0, (double)v0*v1, (double)v0*v2,
                    (double)v1*v1, (double)v1*v2, (double)v2*v2 };
#pragma unroll
    for (int v = 0; v < 9; v++) {
        double x = a[v];
        for (int off = 16; off; off >>= 1) x += __shfl_down_sync(0xffffffffu, x, off);
        a[v] = x;
    }
    if ((threadIdx.x & 31) == 0) {
        atomicAdd(&g_m1[0], a[0]); atomicAdd(&g_m1[1], a[1]); atomicAdd(&g_m1[2], a[2]);
        atomicAdd(&g_m2[0], a[3]); atomicAdd(&g_m2[1], a[4]); atomicAdd(&g_m2[2], a[5]);
        atomicAdd(&g_m2[3], a[6]); atomicAdd(&g_m2[4], a[7]); atomicAdd(&g_m2[5], a[8]);
    }
}

__global__ void finalize3_kernel(const float* __restrict__ W3, const float* __restrict__ gam,
                                 const float* __restrict__ bet, int which, double invcnt) {
    int c = threadIdx.x;
    double w0 = W3[3*c], w1 = W3[3*c+1], w2 = W3[3*c+2];
    double mean = (g_m1[0]*w0 + g_m1[1]*w1 + g_m1[2]*w2) * invcnt;
    double e2 = (w0*w0*g_m2[0] + w1*w1*g_m2[3] + w2*w2*g_m2[5]
                 + 2.0*(w0*w1*g_m2[1] + w0*w2*g_m2[2] + w1*w2*g_m2[4])) * invcnt;
    double var = e2 - mean*mean;
    double s = (double)gam[c] * rsqrt(var + 1e-5);
    float sc = (float)s, sh = (float)((double)bet[c] - mean*s);
    if (which == 0) { g_scps[c] = sc; g_shps[c] = sh; }
    else            { g_scpe[c] = sc; g_shpe[c] = sh; }
}

// ---------------- fused gather + pos-conv-BN-relu + max over K ------------------
__global__ void __launch_bounds__(128) agg_kernel(const float* __restrict__ feats, int np,
        const float* __restrict__ pts, const float* __restrict__ cent,
        const int* __restrict__ nbr, const float* __restrict__ W3, int which,
        float R, float* __restrict__ out) {
    int bm = blockIdx.x;
    int b = bm >> 11;
    int c = threadIdx.x;
    __shared__ int   sj[KK];
    __shared__ float sg[KK][3];
    if (c < KK) {
        int j = nbr[(size_t)bm*KK + c];
        sj[c] = j;
        float cx = cent[(size_t)bm*3], cy = cent[(size_t)bm*3+1], cz = cent[(size_t)bm*3+2];
        const float* p = pts + ((size_t)b*np + j) * 3;
        sg[c][0] = (p[0]-cx)/R; sg[c][1] = (p[1]-cy)/R; sg[c][2] = (p[2]-cz)/R;
    }
    __syncthreads();
    float w0 = W3[3*c], w1 = W3[3*c+1], w2 = W3[3*c+2];
    float sc = which ? g_scpe[c] : g_scps[c];
    float sh = which ? g_shpe[c] : g_shps[c];
    const float* F = feats + (size_t)b * np * 128 + c;
    float acc = -3.4e38f;
#pragma unroll
    for (int k = 0; k < KK; k++) {
        float dot = fmaf(w2, sg[k][2], fmaf(w1, sg[k][1], w0 * sg[k][0]));
        float pev = fmaxf(fmaf(sc, dot, sh), 0.f);
        float gf = F[(size_t)sj[k] * 128];
        acc = fmaxf(acc, gf + pev);
    }
    out[(size_t)bm*128 + c] = acc;
}

// ---------------- residual: relu(feats_i + bn(y2b)) ------------------------------
__global__ void resid_kernel(const float* __restrict__ fi, const float* __restrict__ y,
                             float* __restrict__ out, int ntot) {
    int i = blockIdx.x * blockDim.x + threadIdx.x;
    if (i < ntot) {
        int c = i & 127;
        out[i] = fmaxf(fi[i] + fmaf(y[i], g_scale[c], g_shift[c]), 0.f);
    }
}

// =================================================================================
extern "C" void kernel_launch(void* const* d_in, const int* in_sizes, int n_in,
                              void* d_out, int out_size) {
    const float* pos  = (const float*)d_in[0];
    const float* x    = (const float*)d_in[1];
    const float* W_x  = (const float*)d_in[2];
    const float* gx   = (const float*)d_in[3];
    const float* bx   = (const float*)d_in[4];
    const float* W_ps = (const float*)d_in[5];
    const float* gps  = (const float*)d_in[6];
    const float* bps  = (const float*)d_in[7];
    const float* W_pe = (const float*)d_in[8];
    const float* gpe  = (const float*)d_in[9];
    const float* bpe  = (const float*)d_in[10];
    const float* W1   = (const float*)d_in[11];
    const float* g1   = (const float*)d_in[12];
    const float* b1   = (const float*)d_in[13];
    const float* W2a  = (const float*)d_in[14];
    const float* g2a  = (const float*)d_in[15];
    const float* b2a  = (const float*)d_in[16];
    const float* W2b  = (const float*)d_in[17];
    const float* g2b  = (const float*)d_in[18];
    const float* b2b  = (const float*)d_in[19];

    float* out = (float*)d_out;
    float* cent;
    float* xf_out;
    float* centbuf;
    cudaGetSymbolAddress((void**)&centbuf, g_centbuf);
    if (out_size == BB*MM*3 + BB*MM*CC) { cent = out; xf_out = out + BB*MM*3; }
    else                                { cent = centbuf; xf_out = out; }

    float *feats, *xf, *t1, *t2;
    int *nbr1, *nbr2;
    cudaGetSymbolAddress((void**)&feats, g_feats);
    cudaGetSymbolAddress((void**)&xf,    g_xf);
    cudaGetSymbolAddress((void**)&t1,    g_t1);
    cudaGetSymbolAddress((void**)&t2,    g_t2);
    cudaGetSymbolAddress((void**)&nbr1,  g_nbr1);
    cudaGetSymbolAddress((void**)&nbr2,  g_nbr2);

    const int smem64  = (64*128  + 32*64 ) * 4;
    const int smem128 = (128*128 + 32*128) * 4;
    cudaFuncSetAttribute(gemm_kernel<64>,  cudaFuncAttributeMaxDynamicSharedMemorySize, smem64);
    cudaFuncSetAttribute(gemm_kernel<128>, cudaFuncAttributeMaxDynamicSharedMemorySize, smem128);

    // 1) FPS -> centroids
    fps_kernel<<<BB, 1024>>>(pos, cent);

    // 2) x_mlp: GEMM + BN + relu -> feats (b,n,C)
    gemm_kernel<64><<<(BB*NN)/32, 128, smem64>>>(x, W_x, feats);
    zero_stats_kernel<<<1, 128>>>();
    stats_kernel<<<(BB*NN)/64, 128>>>(feats, 64);
    finalize_kernel<<<1, 128>>>(gx, bx, 1.0 / (BB*NN));
    affine_relu_kernel<<<(BB*NN*CC)/256, 256>>>(feats, BB*NN*CC);

    // 3) ball queries (exact f32(0.01)/f32(0.04) thresholds)
    bq_kernel<<<(BB*MM*32)/256, 256>>>(cent, pos,  NN, 0.01f, nbr1);
    bq_kernel<<<(BB*MM*32)/256, 256>>>(cent, cent, MM, 0.04f, nbr2);

    // 4) analytic BN params for W_ps (stage-1 pos conv) and W_pe (pe)
    zero_moments_kernel<<<1, 32>>>();
    moments_kernel<<<(BB*MM*KK)/256, 256>>>(nbr1, pos, cent, 0.1f, NN);
    finalize3_kernel<<<1, 128>>>(W_ps, gps, bps, 0, 1.0 / (BB*MM*KK));
    zero_moments_kernel<<<1, 32>>>();
    moments_kernel<<<(BB*MM*KK)/256, 256>>>(nbr2, cent, cent, 0.2f, MM);
    finalize3_kernel<<<1, 128>>>(W_pe, gpe, bpe, 1, 1.0 / (BB*MM*KK));

    // 5) stage-1 aggregation -> xf (b,m,C)
    agg_kernel<<<BB*MM, 128>>>(feats, NN, pos, cent, nbr1, W_ps, 0, 0.1f, xf);

    // 6) InvResMLP blocks
    for (int i = 0; i < LL; i++) {
        gemm_kernel<128><<<(BB*MM)/32, 128, smem128>>>(xf, W1 + i*CC*CC, t1);
        zero_stats_kernel<<<1, 128>>>();
        stats_kernel<<<(BB*MM)/64, 128>>>(t1, 64);
        finalize_kernel<<<1, 128>>>(g1 + i*CC, b1 + i*CC, 1.0 / (BB*MM));
        affine_relu_kernel<<<(BB*MM*CC)/256, 256>>>(t1, BB*MM*CC);   // t1 = feats_i

        agg_kernel<<<BB*MM, 128>>>(t1, MM, cent, cent, nbr2, W_pe, 1, 0.2f, t2);

        gemm_kernel<128><<<(BB*MM)/32, 128, smem128>>>(t2, W2a + i*CC*CC, xf);
        zero_stats_kernel<<<1, 128>>>();
        stats_kernel<<<(BB*MM)/64, 128>>>(xf, 64);
        finalize_kernel<<<1, 128>>>(g2a + i*CC, b2a + i*CC, 1.0 / (BB*MM));
        affine_relu_kernel<<<(BB*MM*CC)/256, 256>>>(xf, BB*MM*CC);

        gemm_kernel<128><<<(BB*MM)/32, 128, smem128>>>(xf, W2b + i*CC*CC, t2);
        zero_stats_kernel<<<1, 128>>>();
        stats_kernel<<<(BB*MM)/64, 128>>>(t2, 64);
        finalize_kernel<<<1, 128>>>(g2b + i*CC, b2b + i*CC, 1.0 / (BB*MM));

        float* dst = (i == LL - 1) ? xf_out : xf;
        resid_kernel<<<(BB*MM*CC)/256, 256>>>(t1, t2, dst, BB*MM*CC);
    }
}

// round 2
// speedup vs baseline: 1.0672x; 1.0672x over previous
#include <cuda_runtime.h>
#include <cstdint>

#define BB 4
#define NN 8192
#define CIN 64
#define CC 128
#define MM 2048
#define KK 32
#define LL 2

typedef unsigned long long ull;

// ---------------- scratch (static device globals; no allocation) ----------------
__device__ float  g_feats[BB*NN*CC];
__device__ float  g_xf[BB*MM*CC];
__device__ float  g_t1[BB*MM*CC];
__device__ float  g_t2[BB*MM*CC];
__device__ float  g_centbuf[BB*MM*3];
__device__ int    g_nbr1[BB*MM*KK];
__device__ int    g_nbr2[BB*MM*KK];
__device__ double g_sum[CC], g_sqs[CC];
__device__ double g_m1[3],  g_m2[6];
__device__ float  g_scale[CC], g_shift[CC];
__device__ float  g_scps[CC], g_shps[CC];
__device__ float  g_scpe[CC], g_shpe[CC];

// ---------------- f32x2 packed helpers ------------------------------------------
__device__ __forceinline__ ull pk2(float a, float b) {
    ull r; asm("mov.b64 %0,{%1,%2};" : "=l"(r) : "f"(a), "f"(b)); return r;
}
__device__ __forceinline__ void upk2(ull v, float& a, float& b) {
    asm("mov.b64 {%0,%1},%2;" : "=f"(a), "=f"(b) : "l"(v));
}
__device__ __forceinline__ ull add2(ull a, ull b) {
    ull r; asm("add.rn.f32x2 %0,%1,%2;" : "=l"(r) : "l"(a), "l"(b)); return r;
}
__device__ __forceinline__ ull mul2(ull a, ull b) {
    ull r; asm("mul.rn.f32x2 %0,%1,%2;" : "=l"(r) : "l"(a), "l"(b)); return r;
}

// ---------------- FPS: exact match of jax scan, f32x2 inner loop ----------------
__global__ void __launch_bounds__(1024) fps_kernel(const float* __restrict__ pos,
                                                   float* __restrict__ cent) {
    int b = blockIdx.x;
    const float* P = pos + (size_t)b * NN * 3;
    int t = threadIdx.x;
    // 8 points per thread: indices t + q*1024, q=0..7; packed as 4 pairs
    ull pxp[4], pyp[4], pzp[4];
    float dd[8];
#pragma unroll
    for (int jp = 0; jp < 4; jp++) {
        int i0 = t + (2*jp)   * 1024;
        int i1 = t + (2*jp+1) * 1024;
        pxp[jp] = pk2(P[i0*3],   P[i1*3]);
        pyp[jp] = pk2(P[i0*3+1], P[i1*3+1]);
        pzp[jp] = pk2(P[i0*3+2], P[i1*3+2]);
        dd[2*jp] = 1e10f; dd[2*jp+1] = 1e10f;
    }
    __shared__ ull   red[32];
    __shared__ int   s_last;
    __shared__ float s_lp[3];
    if (t == 0) s_last = 0;
    __syncthreads();

    for (int m = 0; m < MM; m++) {
        if (t == 0) {
            int l = s_last;
            float lx = P[l*3], ly = P[l*3+1], lz = P[l*3+2];
            s_lp[0] = lx; s_lp[1] = ly; s_lp[2] = lz;
            float* co = cent + ((size_t)b*MM + m) * 3;
            co[0] = lx; co[1] = ly; co[2] = lz;
        }
        __syncthreads();
        float nlx = -s_lp[0], nly = -s_lp[1], nlz = -s_lp[2];
        ull nlx2 = pk2(nlx, nlx), nly2 = pk2(nly, nly), nlz2 = pk2(nlz, nlz);
#pragma unroll
        for (int jp = 0; jp < 4; jp++) {
            // exact (px - lx) as px + (-lx); ((dx^2+dy^2)+dz^2) with .rn mul/add
            ull dx = add2(pxp[jp], nlx2);
            ull dy = add2(pyp[jp], nly2);
            ull dz = add2(pzp[jp], nlz2);
            ull s  = add2(add2(mul2(dx, dx), mul2(dy, dy)), mul2(dz, dz));
            float d0, d1; upk2(s, d0, d1);
            dd[2*jp]   = fminf(dd[2*jp],   d0);
            dd[2*jp+1] = fminf(dd[2*jp+1], d1);
        }
        // per-thread argmax (strict > keeps smallest q = smallest global index)
        float bv = dd[0]; int bq = 0;
#pragma unroll
        for (int q = 1; q < 8; q++) { if (dd[q] > bv) { bv = dd[q]; bq = q; } }
        int idx = t + (bq << 10);
        ull best = ((ull)__float_as_uint(bv) << 32) | (unsigned)(NN - idx);
#pragma unroll
        for (int off = 16; off > 0; off >>= 1) {
            ull o = __shfl_down_sync(0xffffffffu, best, off);
            best = best > o ? best : o;
        }
        int lane = t & 31, wid = t >> 5;
        if (lane == 0) red[wid] = best;
        __syncthreads();
        if (wid == 0) {
            ull v = red[lane];
#pragma unroll
            for (int off = 16; off > 0; off >>= 1) {
                ull o = __shfl_down_sync(0xffffffffu, v, off);
                v = v > o ? v : o;
            }
            if (lane == 0) s_last = NN - (int)(v & 0xffffffffull);
        }
        __syncthreads();
    }
}

// ------- GEMM Y[r,o] = sum_c A[r,c]*W[o,c], fused BN-stats + optional pre-affine -
template <int CINT>
__global__ void __launch_bounds__(128) gemm_kernel(const float* __restrict__ A,
                                                   const float* __restrict__ W,
                                                   float* __restrict__ Y,
                                                   int preaffine) {
    extern __shared__ float sm[];
    float* Wt = sm;             // [CINT][128] transposed
    float* At = sm + CINT*128;  // [32][CINT]
    int t = threadIdx.x;
    for (int idx = t; idx < 128*CINT; idx += 128) {
        int o = idx / CINT, c = idx - o*CINT;
        Wt[c*128 + o] = W[idx];
    }
    size_t row0 = (size_t)blockIdx.x * 32;
    const float* Ab = A + row0 * CINT;
    if (preaffine) {
        for (int idx = t; idx < 32*CINT; idx += 128) {
            int c = idx & (CINT - 1);
            At[idx] = fmaxf(fmaf(Ab[idx], g_scale[c], g_shift[c]), 0.f);
        }
    } else {
        for (int idx = t; idx < 32*CINT; idx += 128) At[idx] = Ab[idx];
    }
    __syncthreads();
    float acc[32];
#pragma unroll
    for (int r = 0; r < 32; r++) acc[r] = 0.f;
    for (int c = 0; c < CINT; c++) {
        float w = Wt[c*128 + t];
#pragma unroll
        for (int r = 0; r < 32; r++) acc[r] = fmaf(At[r*CINT + c], w, acc[r]);
    }
    float s = 0.f, q = 0.f;
#pragma unroll
    for (int r = 0; r < 32; r++) {
        Y[(row0 + r)*128 + t] = acc[r];
        s += acc[r]; q = fmaf(acc[r], acc[r], q);
    }
    atomicAdd(&g_sum[t], (double)s);
    atomicAdd(&g_sqs[t], (double)q);
}

// ---------------- init: zero all accumulators once per call ---------------------
__global__ void init_kernel() {
    int t = threadIdx.x;
    g_sum[t] = 0.0; g_sqs[t] = 0.0;
    if (t < 3) g_m1[t] = 0.0;
    if (t < 6) g_m2[t] = 0.0;
}

// ---------------- BN finalize: compute scale/shift, self-reset accumulators -----
__global__ void finalize_kernel(const float* __restrict__ gam,
                                const float* __restrict__ bet, double invcnt) {
    int c = threadIdx.x;
    double mean = g_sum[c] * invcnt;
    double var  = g_sqs[c] * invcnt - mean * mean;
    double s = (double)gam[c] * rsqrt(var + 1e-5);
    g_scale[c] = (float)s;
    g_shift[c] = (float)((double)bet[c] - mean * s);
    g_sum[c] = 0.0; g_sqs[c] = 0.0;
}

__global__ void affine_relu_kernel(float* __restrict__ X, int ntot) {
    int i = blockIdx.x * blockDim.x + threadIdx.x;
    if (i < ntot) {
        int c = i & 127;
        X[i] = fmaxf(fmaf(X[i], g_scale[c], g_shift[c]), 0.f);
    }
}

// ---------------- ball query: first K indices with d2 < r2 (exact) --------------
__global__ void bq_kernel(const float* __restrict__ q, const float* __restrict__ pts,
                          int np, float r2, int* __restrict__ nbr) {
    int gw = (blockIdx.x * blockDim.x + threadIdx.x) >> 5;
    int lane = threadIdx.x & 31;
    if (gw >= BB*MM) return;
    int b = gw >> 11;
    const float* Q = q + (size_t)gw * 3;
    float qx = Q[0], qy = Q[1], qz = Q[2];
    const float* P = pts + (size_t)b * np * 3;
    int cnt = 0, first = 0;
    for (int base = 0; base < np; base += 32) {
        int i = base + lane;
        float dx = qx - P[i*3], dy = qy - P[i*3+1], dz = qz - P[i*3+2];
        float d2 = __fadd_rn(__fadd_rn(__fmul_rn(dx,dx), __fmul_rn(dy,dy)),
                             __fmul_rn(dz,dz));
        bool pred = d2 < r2;
        unsigned mask = __ballot_sync(0xffffffffu, pred);
        if (cnt == 0 && mask) first = base + __ffs(mask) - 1;
        if (pred) {
            int pos = cnt + __popc(mask & ((1u << lane) - 1u));
            if (pos < KK) nbr[(size_t)gw*KK + pos] = i;
        }
        cnt += __popc(mask);
        if (cnt >= KK) break;
    }
    for (int k = cnt + lane; k < KK; k += 32) nbr[(size_t)gw*KK + k] = first;
}

// ---------------- 3-dim offset moments (analytic BN of W_ps/W_pe convs) ---------
__global__ void moments_kernel(const int* __restrict__ nbr, const float* __restrict__ pts,
                               const float* __restrict__ cent, float R, int np) {
    int idx = blockIdx.x * blockDim.x + threadIdx.x;
    int bm = idx / KK;
    int b = bm >> 11;
    int j = nbr[idx];
    float cx = cent[(size_t)bm*3], cy = cent[(size_t)bm*3+1], cz = cent[(size_t)bm*3+2];
    const float* p = pts + ((size_t)b*np + j) * 3;
    float v0 = (p[0]-cx)/R, v1 = (p[1]-cy)/R, v2 = (p[2]-cz)/R;
    double a[9] = { v0, v1, v2,
                    (double)v0*v0, (double)v0*v1, (double)v0*v2,
                    (double)v1*v1, (double)v1*v2, (double)v2*v2 };
#pragma unroll
    for (int v = 0; v < 9; v++) {
        double x = a[v];
        for (int off = 16; off; off >>= 1) x += __shfl_down_sync(0xffffffffu, x, off);
        a[v] = x;
    }
    if ((threadIdx.x & 31) == 0) {
        atomicAdd(&g_m1[0], a[0]); atomicAdd(&g_m1[1], a[1]); atomicAdd(&g_m1[2], a[2]);
        atomicAdd(&g_m2[0], a[3]); atomicAdd(&g_m2[1], a[4]); atomicAdd(&g_m2[2], a[5]);
        atomicAdd(&g_m2[3], a[6]); atomicAdd(&g_m2[4], a[7]); atomicAdd(&g_m2[5], a[8]);
    }
}

__global__ void finalize3_kernel(const float* __restrict__ W3, const float* __restrict__ gam,
                                 const float* __restrict__ bet, int which, double invcnt) {
    int c = threadIdx.x;
    double w0 = W3[3*c], w1 = W3[3*c+1], w2 = W3[3*c+2];
    double mean = (g_m1[0]*w0 + g_m1[1]*w1 + g_m1[2]*w2) * invcnt;
    double e2 = (w0*w0*g_m2[0] + w1*w1*g_m2[3] + w2*w2*g_m2[5]
                 + 2.0*(w0*w1*g_m2[1] + w0*w2*g_m2[2] + w1*w2*g_m2[4])) * invcnt;
    double var = e2 - mean*mean;
    double s = (double)gam[c] * rsqrt(var + 1e-5);
    float sc = (float)s, sh = (float)((double)bet[c] - mean*s);
    if (which == 0) { g_scps[c] = sc; g_shps[c] = sh; }
    else            { g_scpe[c] = sc; g_shpe[c] = sh; }
    __syncthreads();
    if (c < 3) g_m1[c] = 0.0;
    if (c < 6) g_m2[c] = 0.0;
}

// ---------------- fused gather + pos-conv-BN-relu + max over K ------------------
__global__ void __launch_bounds__(128) agg_kernel(const float* __restrict__ feats, int np,
        const float* __restrict__ pts, const float* __restrict__ cent,
        const int* __restrict__ nbr, const float* __restrict__ W3, int which,
        float R, float* __restrict__ out) {
    int bm = blockIdx.x;
    int b = bm >> 11;
    int c = threadIdx.x;
    __shared__ int   sj[KK];
    __shared__ float sg[KK][3];
    if (c < KK) {
        int j = nbr[(size_t)bm*KK + c];
        sj[c] = j;
        float cx = cent[(size_t)bm*3], cy = cent[(size_t)bm*3+1], cz = cent[(size_t)bm*3+2];
        const float* p = pts + ((size_t)b*np + j) * 3;
        sg[c][0] = (p[0]-cx)/R; sg[c][1] = (p[1]-cy)/R; sg[c][2] = (p[2]-cz)/R;
    }
    __syncthreads();
    float w0 = W3[3*c], w1 = W3[3*c+1], w2 = W3[3*c+2];
    float sc = which ? g_scpe[c] : g_scps[c];
    float sh = which ? g_shpe[c] : g_shps[c];
    const float* F = feats + (size_t)b * np * 128 + c;
    float acc = -3.4e38f;
#pragma unroll
    for (int k = 0; k < KK; k++) {
        float dot = fmaf(w2, sg[k][2], fmaf(w1, sg[k][1], w0 * sg[k][0]));
        float pev = fmaxf(fmaf(sc, dot, sh), 0.f);
        float gf = F[(size_t)sj[k] * 128];
        acc = fmaxf(acc, gf + pev);
    }
    out[(size_t)bm*128 + c] = acc;
}

// ---------------- residual: relu(feats_i + bn(y2b)) ------------------------------
__global__ void resid_kernel(const float* __restrict__ fi, const float* __restrict__ y,
                             float* __restrict__ out, int ntot) {
    int i = blockIdx.x * blockDim.x + threadIdx.x;
    if (i < ntot) {
        int c = i & 127;
        out[i] = fmaxf(fi[i] + fmaf(y[i], g_scale[c], g_shift[c]), 0.f);
    }
}

// =================================================================================
extern "C" void kernel_launch(void* const* d_in, const int* in_sizes, int n_in,
                              void* d_out, int out_size) {
    const float* pos  = (const float*)d_in[0];
    const float* x    = (const float*)d_in[1];
    const float* W_x  = (const float*)d_in[2];
    const float* gx   = (const float*)d_in[3];
    const float* bx   = (const float*)d_in[4];
    const float* W_ps = (const float*)d_in[5];
    const float* gps  = (const float*)d_in[6];
    const float* bps  = (const float*)d_in[7];
    const float* W_pe = (const float*)d_in[8];
    const float* gpe  = (const float*)d_in[9];
    const float* bpe  = (const float*)d_in[10];
    const float* W1   = (const float*)d_in[11];
    const float* g1   = (const float*)d_in[12];
    const float* b1   = (const float*)d_in[13];
    const float* W2a  = (const float*)d_in[14];
    const float* g2a  = (const float*)d_in[15];
    const float* b2a  = (const float*)d_in[16];
    const float* W2b  = (const float*)d_in[17];
    const float* g2b  = (const float*)d_in[18];
    const float* b2b  = (const float*)d_in[19];

    float* out = (float*)d_out;
    float* cent;
    float* xf_out;
    float* centbuf;
    cudaGetSymbolAddress((void**)&centbuf, g_centbuf);
    if (out_size == BB*MM*3 + BB*MM*CC) { cent = out; xf_out = out + BB*MM*3; }
    else                                { cent = centbuf; xf_out = out; }

    float *feats, *xf, *t1, *t2;
    int *nbr1, *nbr2;
    cudaGetSymbolAddress((void**)&feats, g_feats);
    cudaGetSymbolAddress((void**)&xf,    g_xf);
    cudaGetSymbolAddress((void**)&t1,    g_t1);
    cudaGetSymbolAddress((void**)&t2,    g_t2);
    cudaGetSymbolAddress((void**)&nbr1,  g_nbr1);
    cudaGetSymbolAddress((void**)&nbr2,  g_nbr2);

    const int smem64  = (64*128  + 32*64 ) * 4;
    const int smem128 = (128*128 + 32*128) * 4;
    cudaFuncSetAttribute(gemm_kernel<64>,  cudaFuncAttributeMaxDynamicSharedMemorySize, smem64);
    cudaFuncSetAttribute(gemm_kernel<128>, cudaFuncAttributeMaxDynamicSharedMemorySize, smem128);

    init_kernel<<<1, 128>>>();

    // 1) FPS -> centroids
    fps_kernel<<<BB, 1024>>>(pos, cent);

    // 2) x_mlp: GEMM(+stats) + finalize + affine-relu -> feats (b,n,C)
    gemm_kernel<64><<<(BB*NN)/32, 128, smem64>>>(x, W_x, feats, 0);
    finalize_kernel<<<1, 128>>>(gx, bx, 1.0 / (BB*NN));
    affine_relu_kernel<<<(BB*NN*CC)/256, 256>>>(feats, BB*NN*CC);

    // 3) ball queries (exact f32(0.01)/f32(0.04) thresholds)
    bq_kernel<<<(BB*MM*32)/256, 256>>>(cent, pos,  NN, 0.01f, nbr1);
    bq_kernel<<<(BB*MM*32)/256, 256>>>(cent, cent, MM, 0.04f, nbr2);

    // 4) analytic BN params for W_ps and W_pe
    moments_kernel<<<(BB*MM*KK)/256, 256>>>(nbr1, pos, cent, 0.1f, NN);
    finalize3_kernel<<<1, 128>>>(W_ps, gps, bps, 0, 1.0 / (BB*MM*KK));
    moments_kernel<<<(BB*MM*KK)/256, 256>>>(nbr2, cent, cent, 0.2f, MM);
    finalize3_kernel<<<1, 128>>>(W_pe, gpe, bpe, 1, 1.0 / (BB*MM*KK));

    // 5) stage-1 aggregation -> xf (b,m,C)
    agg_kernel<<<BB*MM, 128>>>(feats, NN, pos, cent, nbr1, W_ps, 0, 0.1f, xf);

    // 6) InvResMLP blocks
    for (int i = 0; i < LL; i++) {
        gemm_kernel<128><<<(BB*MM)/32, 128, smem128>>>(xf, W1 + i*CC*CC, t1, 0);
        finalize_kernel<<<1, 128>>>(g1 + i*CC, b1 + i*CC, 1.0 / (BB*MM));
        affine_relu_kernel<<<(BB*MM*CC)/256, 256>>>(t1, BB*MM*CC);   // t1 = feats_i

        agg_kernel<<<BB*MM, 128>>>(t1, MM, cent, cent, nbr2, W_pe, 1, 0.2f, t2);

        gemm_kernel<128><<<(BB*MM)/32, 128, smem128>>>(t2, W2a + i*CC*CC, xf, 0);
        finalize_kernel<<<1, 128>>>(g2a + i*CC, b2a + i*CC, 1.0 / (BB*MM));

        // pre-affine(relu(bn)) applied on load inside the W2b GEMM
        gemm_kernel<128><<<(BB*MM)/32, 128, smem128>>>(xf, W2b + i*CC*CC, t2, 1);
        finalize_kernel<<<1, 128>>>(g2b + i*CC, b2b + i*CC, 1.0 / (BB*MM));

        float* dst = (i == LL - 1) ? xf_out : xf;
        resid_kernel<<<(BB*MM*CC)/256, 256>>>(t1, t2, dst, BB*MM*CC);
    }
}

// round 3
// speedup vs baseline: 1.0937x; 1.0248x over previous
#include <cuda_runtime.h>
#include <cstdint>

#define BB 4
#define NN 8192
#define CIN 64
#define CC 128
#define MM 2048
#define KK 32
#define LL 2

typedef unsigned long long ull;

// ---------------- scratch (static device globals; no allocation) ----------------
__device__ float  g_feats[BB*NN*CC];
__device__ float  g_xf[BB*MM*CC];
__device__ float  g_t1[BB*MM*CC];
__device__ float  g_t2[BB*MM*CC];
__device__ float  g_centbuf[BB*MM*3];
__device__ int    g_nbr1[BB*MM*KK];
__device__ int    g_nbr2[BB*MM*KK];
__device__ double g_sum[CC], g_sqs[CC];
__device__ double g_m1a[3], g_m2a[6], g_m1b[3], g_m2b[6];
__device__ float  g_scA[CC], g_shA[CC];   // slot A (x_mlp / W1 per-iter)
__device__ float  g_scB[CC], g_shB[CC];   // slot B (W2a)
__device__ float  g_scC[CC], g_shC[CC];   // slot C (W2b)
__device__ float  g_scps[CC], g_shps[CC];
__device__ float  g_scpe[CC], g_shpe[CC];

// ---------------- packed helpers -------------------------------------------------
__device__ __forceinline__ ull pk2(float a, float b) {
    ull r; asm("mov.b64 %0,{%1,%2};" : "=l"(r) : "f"(a), "f"(b)); return r;
}
__device__ __forceinline__ void upk2(ull v, float& a, float& b) {
    asm("mov.b64 {%0,%1},%2;" : "=f"(a), "=f"(b) : "l"(v));
}
__device__ __forceinline__ ull fma2(ull a, ull b, ull c) {
    ull r; asm("fma.rn.f32x2 %0,%1,%2,%3;" : "=l"(r) : "l"(a), "l"(b), "l"(c)); return r;
}

// ---------------- FPS: exact jax-scan match, FFMA2 inner loop, 2 bars/iter ------
__global__ void __launch_bounds__(1024) fps_kernel(const float* __restrict__ pos,
                                                   float* __restrict__ cent) {
    int b = blockIdx.x;
    const float* P = pos + (size_t)b * NN * 3;
    int t = threadIdx.x;
    ull pxp[4], pyp[4], pzp[4];
    float dd[8];
#pragma unroll
    for (int jp = 0; jp < 4; jp++) {
        int i0 = t + (2*jp)   * 1024;
        int i1 = t + (2*jp+1) * 1024;
        pxp[jp] = pk2(P[i0*3],   P[i1*3]);
        pyp[jp] = pk2(P[i0*3+1], P[i1*3+1]);
        pzp[jp] = pk2(P[i0*3+2], P[i1*3+2]);
        dd[2*jp] = 1e10f; dd[2*jp+1] = 1e10f;
    }
    __shared__ ull   red[32];
    __shared__ float s_lp[3];
    float lx = P[0], ly = P[1], lz = P[2];
    if (t == 0) {
        float* c0 = cent + (size_t)b*MM*3;
        c0[0] = lx; c0[1] = ly; c0[2] = lz;
    }
    const ull ONE2 = pk2(1.0f, 1.0f);
    int lane = t & 31, wid = t >> 5;

    for (int m = 1; m < MM; m++) {
        ull nlx2 = pk2(-lx, -lx), nly2 = pk2(-ly, -ly), nlz2 = pk2(-lz, -lz);
#pragma unroll
        for (int jp = 0; jp < 4; jp++) {
            // all FFMA2, each exactly reproducing the scalar .rn op sequence:
            // dx = round(px - lx); sq = round(dx^2); s = round(sq + acc)
            ull dx = fma2(pxp[jp], ONE2, nlx2);
            ull dy = fma2(pyp[jp], ONE2, nly2);
            ull dz = fma2(pzp[jp], ONE2, nlz2);
            ull sx = fma2(dx, dx, 0ull);
            ull sy = fma2(dy, dy, 0ull);
            ull sz = fma2(dz, dz, 0ull);
            ull s  = fma2(sz, ONE2, fma2(sy, ONE2, sx));
            float d0, d1; upk2(s, d0, d1);
            dd[2*jp]   = fminf(dd[2*jp],   d0);
            dd[2*jp+1] = fminf(dd[2*jp+1], d1);
        }
        // per-thread argmax (strict > keeps smallest q = smallest global index)
        float bv = dd[0]; int bq = 0;
#pragma unroll
        for (int q = 1; q < 8; q++) { if (dd[q] > bv) { bv = dd[q]; bq = q; } }
        int idx = t + (bq << 10);
        ull best = ((ull)__float_as_uint(bv) << 32) | (unsigned)(NN - idx);
#pragma unroll
        for (int off = 16; off > 0; off >>= 1) {
            ull o = __shfl_down_sync(0xffffffffu, best, off);
            best = best > o ? best : o;
        }
        if (lane == 0) red[wid] = best;
        __syncthreads();
        if (wid == 0) {
            ull v = red[lane];
#pragma unroll
            for (int off = 16; off > 0; off >>= 1) {
                ull o = __shfl_down_sync(0xffffffffu, v, off);
                v = v > o ? v : o;
            }
            if (lane == 0) {
                int sel = NN - (int)(v & 0xffffffffull);
                float ax = P[sel*3], ay = P[sel*3+1], az = P[sel*3+2];
                s_lp[0] = ax; s_lp[1] = ay; s_lp[2] = az;
                float* co = cent + ((size_t)b*MM + m) * 3;
                co[0] = ax; co[1] = ay; co[2] = az;
            }
        }
        __syncthreads();
        lx = s_lp[0]; ly = s_lp[1]; lz = s_lp[2];
    }
}

// ------- GEMM Y[r,o] = sum_c A[r,c]*W[o,c], fused BN-stats + optional pre-affine -
template <int CINT>
__global__ void __launch_bounds__(128) gemm_kernel(const float* __restrict__ A,
                                                   const float* __restrict__ W,
                                                   float* __restrict__ Y,
                                                   const float* __restrict__ preSc,
                                                   const float* __restrict__ preSh) {
    extern __shared__ float sm[];
    float* Wt = sm;             // [CINT][128] transposed
    float* At = sm + CINT*128;  // [32][CINT]
    int t = threadIdx.x;
    for (int idx = t; idx < 128*CINT; idx += 128) {
        int o = idx / CINT, c = idx - o*CINT;
        Wt[c*128 + o] = W[idx];
    }
    size_t row0 = (size_t)blockIdx.x * 32;
    const float* Ab = A + row0 * CINT;
    if (preSc) {
        for (int idx = t; idx < 32*CINT; idx += 128) {
            int c = idx & (CINT - 1);
            At[idx] = fmaxf(fmaf(Ab[idx], preSc[c], preSh[c]), 0.f);
        }
    } else {
        for (int idx = t; idx < 32*CINT; idx += 128) At[idx] = Ab[idx];
    }
    __syncthreads();
    float acc[32];
#pragma unroll
    for (int r = 0; r < 32; r++) acc[r] = 0.f;
    for (int c = 0; c < CINT; c++) {
        float w = Wt[c*128 + t];
#pragma unroll
        for (int r = 0; r < 32; r++) acc[r] = fmaf(At[r*CINT + c], w, acc[r]);
    }
    float s = 0.f, q = 0.f;
#pragma unroll
    for (int r = 0; r < 32; r++) {
        Y[(row0 + r)*128 + t] = acc[r];
        s += acc[r]; q = fmaf(acc[r], acc[r], q);
    }
    atomicAdd(&g_sum[t], (double)s);
    atomicAdd(&g_sqs[t], (double)q);
}

// ---------------- init: zero all accumulators once per call ---------------------
__global__ void init_kernel() {
    int t = threadIdx.x;
    g_sum[t] = 0.0; g_sqs[t] = 0.0;
    if (t < 3) { g_m1a[t] = 0.0; g_m1b[t] = 0.0; }
    if (t < 6) { g_m2a[t] = 0.0; g_m2b[t] = 0.0; }
}

// ---------------- BN finalize: scale/shift to a slot, self-reset ----------------
__global__ void finalize_kernel(const float* __restrict__ gam,
                                const float* __restrict__ bet, double invcnt,
                                float* __restrict__ outSc, float* __restrict__ outSh) {
    int c = threadIdx.x;
    double mean = g_sum[c] * invcnt;
    double var  = g_sqs[c] * invcnt - mean * mean;
    double s = (double)gam[c] * rsqrt(var + 1e-5);
    outSc[c] = (float)s;
    outSh[c] = (float)((double)bet[c] - mean * s);
    g_sum[c] = 0.0; g_sqs[c] = 0.0;
}

// ---------------- ball query with smem point cache (exact thresholds) ------------
__global__ void __launch_bounds__(256) bq_kernel(const float* __restrict__ q,
        const float* __restrict__ pts, int np, float r2, int* __restrict__ nbr) {
    extern __shared__ float sp[];
    float* sx = sp; float* sy = sp + np; float* sz = sp + 2*np;
    int gw0 = blockIdx.x * 8;
    int b = gw0 >> 11;
    const float* P = pts + (size_t)b * np * 3;
    for (int idx = threadIdx.x; idx < np*3; idx += 256) {
        float v = P[idx];
        int pt = idx / 3, d = idx - pt*3;
        sp[d*np + pt] = v;
    }
    __syncthreads();
    int w = threadIdx.x >> 5, lane = threadIdx.x & 31;
    int gw = gw0 + w;
    const float* Q = q + (size_t)gw * 3;
    float qx = Q[0], qy = Q[1], qz = Q[2];
    int cnt = 0, first = 0;
    for (int base = 0; base < np; base += 32) {
        int i = base + lane;
        float dx = __fadd_rn(qx, -sx[i]), dy = __fadd_rn(qy, -sy[i]), dz = __fadd_rn(qz, -sz[i]);
        float d2 = __fadd_rn(__fadd_rn(__fmul_rn(dx,dx), __fmul_rn(dy,dy)),
                             __fmul_rn(dz,dz));
        bool pred = d2 < r2;
        unsigned mask = __ballot_sync(0xffffffffu, pred);
        if (cnt == 0 && mask) first = base + __ffs(mask) - 1;
        if (pred) {
            int pos = cnt + __popc(mask & ((1u << lane) - 1u));
            if (pos < KK) nbr[(size_t)gw*KK + pos] = i;
        }
        cnt += __popc(mask);
        if (cnt >= KK) break;
    }
    for (int k = cnt + lane; k < KK; k += 32) nbr[(size_t)gw*KK + k] = first;
}

// ---------------- 3-dim offset moments (analytic BN of W_ps/W_pe convs) ---------
__global__ void moments_kernel(const int* __restrict__ nbr, const float* __restrict__ pts,
                               const float* __restrict__ cent, float R, int np,
                               double* __restrict__ m1, double* __restrict__ m2) {
    int idx = blockIdx.x * blockDim.x + threadIdx.x;
    int bm = idx / KK;
    int b = bm >> 11;
    int j = nbr[idx];
    float cx = cent[(size_t)bm*3], cy = cent[(size_t)bm*3+1], cz = cent[(size_t)bm*3+2];
    const float* p = pts + ((size_t)b*np + j) * 3;
    float v0 = (p[0]-cx)/R, v1 = (p[1]-cy)/R, v2 = (p[2]-cz)/R;
    double a[9] = { v0, v1, v2,
                    (double)v0*v0, (double)v0*v1, (double)v0*v2,
                    (double)v1*v1, (double)v1*v2, (double)v2*v2 };
#pragma unroll
    for (int v = 0; v < 9; v++) {
        double x = a[v];
        for (int off = 16; off; off >>= 1) x += __shfl_down_sync(0xffffffffu, x, off);
        a[v] = x;
    }
    if ((threadIdx.x & 31) == 0) {
        atomicAdd(&m1[0], a[0]); atomicAdd(&m1[1], a[1]); atomicAdd(&m1[2], a[2]);
        atomicAdd(&m2[0], a[3]); atomicAdd(&m2[1], a[4]); atomicAdd(&m2[2], a[5]);
        atomicAdd(&m2[3], a[6]); atomicAdd(&m2[4], a[7]); atomicAdd(&m2[5], a[8]);
    }
}

// ---------------- finalize both 3-dim BN params in one launch --------------------
__global__ void finalize3both_kernel(const float* __restrict__ Wps, const float* __restrict__ gps,
                                     const float* __restrict__ bps,
                                     const float* __restrict__ Wpe, const float* __restrict__ gpe,
                                     const float* __restrict__ bpe, double invcnt) {
    int c = threadIdx.x;
    {
        double w0 = Wps[3*c], w1 = Wps[3*c+1], w2 = Wps[3*c+2];
        double mean = (g_m1a[0]*w0 + g_m1a[1]*w1 + g_m1a[2]*w2) * invcnt;
        double e2 = (w0*w0*g_m2a[0] + w1*w1*g_m2a[3] + w2*w2*g_m2a[5]
                     + 2.0*(w0*w1*g_m2a[1] + w0*w2*g_m2a[2] + w1*w2*g_m2a[4])) * invcnt;
        double var = e2 - mean*mean;
        double s = (double)gps[c] * rsqrt(var + 1e-5);
        g_scps[c] = (float)s; g_shps[c] = (float)((double)bps[c] - mean*s);
    }
    {
        double w0 = Wpe[3*c], w1 = Wpe[3*c+1], w2 = Wpe[3*c+2];
        double mean = (g_m1b[0]*w0 + g_m1b[1]*w1 + g_m1b[2]*w2) * invcnt;
        double e2 = (w0*w0*g_m2b[0] + w1*w1*g_m2b[3] + w2*w2*g_m2b[5]
                     + 2.0*(w0*w1*g_m2b[1] + w0*w2*g_m2b[2] + w1*w2*g_m2b[4])) * invcnt;
        double var = e2 - mean*mean;
        double s = (double)gpe[c] * rsqrt(var + 1e-5);
        g_scpe[c] = (float)s; g_shpe[c] = (float)((double)bpe[c] - mean*s);
    }
    __syncthreads();
    if (c < 3) { g_m1a[c] = 0.0; g_m1b[c] = 0.0; }
    if (c < 6) { g_m2a[c] = 0.0; g_m2b[c] = 0.0; }
}

// ------- fused gather(+affine-relu of feats) + pos-conv-BN-relu + max over K -----
__global__ void __launch_bounds__(128) agg_kernel(const float* __restrict__ feats, int np,
        const float* __restrict__ pts, const float* __restrict__ cent,
        const int* __restrict__ nbr, const float* __restrict__ W3, int which,
        float R, const float* __restrict__ aSc, const float* __restrict__ aSh,
        float* __restrict__ out) {
    int bm = blockIdx.x;
    int b = bm >> 11;
    int c = threadIdx.x;
    __shared__ int   sj[KK];
    __shared__ float sg[KK][3];
    if (c < KK) {
        int j = nbr[(size_t)bm*KK + c];
        sj[c] = j;
        float cx = cent[(size_t)bm*3], cy = cent[(size_t)bm*3+1], cz = cent[(size_t)bm*3+2];
        const float* p = pts + ((size_t)b*np + j) * 3;
        sg[c][0] = (p[0]-cx)/R; sg[c][1] = (p[1]-cy)/R; sg[c][2] = (p[2]-cz)/R;
    }
    __syncthreads();
    float w0 = W3[3*c], w1 = W3[3*c+1], w2 = W3[3*c+2];
    float sc = which ? g_scpe[c] : g_scps[c];
    float sh = which ? g_shpe[c] : g_shps[c];
    float asc = aSc[c], ash = aSh[c];
    const float* F = feats + (size_t)b * np * 128 + c;
    float acc = -3.4e38f;
#pragma unroll
    for (int k = 0; k < KK; k++) {
        float dot = fmaf(w2, sg[k][2], fmaf(w1, sg[k][1], w0 * sg[k][0]));
        float pev = fmaxf(fmaf(sc, dot, sh), 0.f);
        float raw = F[(size_t)sj[k] * 128];
        float gf = fmaxf(fmaf(raw, asc, ash), 0.f);
        acc = fmaxf(acc, gf + pev);
    }
    out[(size_t)bm*128 + c] = acc;
}

// ------ residual: relu( relu(affineA(fi_raw)) + affineC(y_raw) ) ----------------
__global__ void resid_kernel(const float* __restrict__ fi, const float* __restrict__ y,
                             float* __restrict__ out, int ntot) {
    int i = blockIdx.x * blockDim.x + threadIdx.x;
    if (i < ntot) {
        int c = i & 127;
        float f = fmaxf(fmaf(fi[i], g_scA[c], g_shA[c]), 0.f);
        out[i] = fmaxf(f + fmaf(y[i], g_scC[c], g_shC[c]), 0.f);
    }
}

// =================================================================================
extern "C" void kernel_launch(void* const* d_in, const int* in_sizes, int n_in,
                              void* d_out, int out_size) {
    const float* pos  = (const float*)d_in[0];
    const float* x    = (const float*)d_in[1];
    const float* W_x  = (const float*)d_in[2];
    const float* gx   = (const float*)d_in[3];
    const float* bx   = (const float*)d_in[4];
    const float* W_ps = (const float*)d_in[5];
    const float* gps  = (const float*)d_in[6];
    const float* bps  = (const float*)d_in[7];
    const float* W_pe = (const float*)d_in[8];
    const float* gpe  = (const float*)d_in[9];
    const float* bpe  = (const float*)d_in[10];
    const float* W1   = (const float*)d_in[11];
    const float* g1   = (const float*)d_in[12];
    const float* b1   = (const float*)d_in[13];
    const float* W2a  = (const float*)d_in[14];
    const float* g2a  = (const float*)d_in[15];
    const float* b2a  = (const float*)d_in[16];
    const float* W2b  = (const float*)d_in[17];
    const float* g2b  = (const float*)d_in[18];
    const float* b2b  = (const float*)d_in[19];

    float* out = (float*)d_out;
    float* cent;
    float* xf_out;
    float* centbuf;
    cudaGetSymbolAddress((void**)&centbuf, g_centbuf);
    if (out_size == BB*MM*3 + BB*MM*CC) { cent = out; xf_out = out + BB*MM*3; }
    else                                { cent = centbuf; xf_out = out; }

    float *feats, *xf, *t1, *t2;
    int *nbr1, *nbr2;
    double *m1a, *m2a, *m1b, *m2b;
    float *scA, *shA, *scB, *shB, *scC, *shC;
    cudaGetSymbolAddress((void**)&feats, g_feats);
    cudaGetSymbolAddress((void**)&xf,    g_xf);
    cudaGetSymbolAddress((void**)&t1,    g_t1);
    cudaGetSymbolAddress((void**)&t2,    g_t2);
    cudaGetSymbolAddress((void**)&nbr1,  g_nbr1);
    cudaGetSymbolAddress((void**)&nbr2,  g_nbr2);
    cudaGetSymbolAddress((void**)&m1a,   g_m1a);
    cudaGetSymbolAddress((void**)&m2a,   g_m2a);
    cudaGetSymbolAddress((void**)&m1b,   g_m1b);
    cudaGetSymbolAddress((void**)&m2b,   g_m2b);
    cudaGetSymbolAddress((void**)&scA,   g_scA);
    cudaGetSymbolAddress((void**)&shA,   g_shA);
    cudaGetSymbolAddress((void**)&scB,   g_scB);
    cudaGetSymbolAddress((void**)&shB,   g_shB);
    cudaGetSymbolAddress((void**)&scC,   g_scC);
    cudaGetSymbolAddress((void**)&shC,   g_shC);

    static cudaStream_t s1 = nullptr, s2 = nullptr;
    static cudaEvent_t eFork, eXmlp, eFps, eS2;
    if (!s1) {
        cudaStreamCreateWithFlags(&s1, cudaStreamNonBlocking);
        cudaStreamCreateWithFlags(&s2, cudaStreamNonBlocking);
        cudaEventCreateWithFlags(&eFork, cudaEventDisableTiming);
        cudaEventCreateWithFlags(&eXmlp, cudaEventDisableTiming);
        cudaEventCreateWithFlags(&eFps,  cudaEventDisableTiming);
        cudaEventCreateWithFlags(&eS2,   cudaEventDisableTiming);
    }

    const int smem64  = (64*128  + 32*64 ) * 4;
    const int smem128 = (128*128 + 32*128) * 4;
    const int smemBQ1 = NN * 3 * 4;
    const int smemBQ2 = MM * 3 * 4;
    cudaFuncSetAttribute(gemm_kernel<64>,  cudaFuncAttributeMaxDynamicSharedMemorySize, smem64);
    cudaFuncSetAttribute(gemm_kernel<128>, cudaFuncAttributeMaxDynamicSharedMemorySize, smem128);
    cudaFuncSetAttribute(bq_kernel,        cudaFuncAttributeMaxDynamicSharedMemorySize, smemBQ1);

    // init accumulators, then fork x_mlp chain onto s1 while FPS runs on default
    init_kernel<<<1, 128>>>();
    cudaEventRecord(eFork, 0);
    cudaStreamWaitEvent(s1, eFork, 0);

    fps_kernel<<<BB, 1024>>>(pos, cent);

    gemm_kernel<64><<<(BB*NN)/32, 128, smem64, s1>>>(x, W_x, feats, nullptr, nullptr);
    finalize_kernel<<<1, 128, 0, s1>>>(gx, bx, 1.0/(BB*NN), scA, shA);
    cudaEventRecord(eXmlp, s1);

    // fork bq2+moments2 onto s2 (needs cent only)
    cudaEventRecord(eFps, 0);
    cudaStreamWaitEvent(s2, eFps, 0);
    bq_kernel<<<(BB*MM)/8, 256, smemBQ2, s2>>>(cent, cent, MM, 0.04f, nbr2);
    moments_kernel<<<(BB*MM*KK)/256, 256, 0, s2>>>(nbr2, cent, cent, 0.2f, MM, m1b, m2b);
    cudaEventRecord(eS2, s2);

    // default: bq1 + moments1
    bq_kernel<<<(BB*MM)/8, 256, smemBQ1>>>(cent, pos, NN, 0.01f, nbr1);
    moments_kernel<<<(BB*MM*KK)/256, 256>>>(nbr1, pos, cent, 0.1f, NN, m1a, m2a);

    // join both side streams
    cudaStreamWaitEvent(0, eS2, 0);
    cudaStreamWaitEvent(0, eXmlp, 0);

    finalize3both_kernel<<<1, 128>>>(W_ps, gps, bps, W_pe, gpe, bpe, 1.0/(BB*MM*KK));

    // stage-1 aggregation (feats affine+relu applied on the fly) -> xf (b,m,C)
    agg_kernel<<<BB*MM, 128>>>(feats, NN, pos, cent, nbr1, W_ps, 0, 0.1f, scA, shA, xf);

    // InvResMLP blocks
    for (int i = 0; i < LL; i++) {
        gemm_kernel<128><<<(BB*MM)/32, 128, smem128>>>(xf, W1 + i*CC*CC, t1, nullptr, nullptr);
        finalize_kernel<<<1, 128>>>(g1 + i*CC, b1 + i*CC, 1.0/(BB*MM), scA, shA);

        // t1 affine+relu applied inside agg (slot A)
        agg_kernel<<<BB*MM, 128>>>(t1, MM, cent, cent, nbr2, W_pe, 1, 0.2f, scA, shA, t2);

        gemm_kernel<128><<<(BB*MM)/32, 128, smem128>>>(t2, W2a + i*CC*CC, xf, nullptr, nullptr);
        finalize_kernel<<<1, 128>>>(g2a + i*CC, b2a + i*CC, 1.0/(BB*MM), scB, shB);

        // W2b GEMM applies relu(affineB) to its input on load
        gemm_kernel<128><<<(BB*MM)/32, 128, smem128>>>(xf, W2b + i*CC*CC, t2, scB, shB);
        finalize_kernel<<<1, 128>>>(g2b + i*CC, b2b + i*CC, 1.0/(BB*MM), scC, shC);

        float* dst = (i == LL - 1) ? xf_out : xf;
        resid_kernel<<<(BB*MM*CC)/256, 256>>>(t1, t2, dst, BB*MM*CC);
    }
}